// round 1
// baseline (speedup 1.0000x reference)
#include <cuda_runtime.h>
#include <cuda_bf16.h>
#include <cstdint>

#define N_NODES 20000
#define N_EDGES 100000
#define DIM 768
#define NUM_REL 4
#define K5  (5*DIM)      // 3840: [x | agg0..agg3]
#define KT2 (2*K5)       // 7680: stored A cols  [hi | lo]
#define KT  (3*K5)       // 11520: logical K     [hi | lo | hi]
#define BK 32
#define NKT (KT/BK)      // 360 k-tiles
#define HI2_TILES (KT2/BK) // 240: tiles covering [hi|lo]; tiles >=240 re-read hi

// ---------------- scratch (static device globals; no runtime allocation) ----
__device__ float g_x0[(size_t)N_NODES*DIM];
__device__ float g_x1[(size_t)N_NODES*DIM];
__device__ float g_agg[(size_t)NUM_REL*N_NODES*DIM];
__device__ __nv_bfloat16 g_A3[(size_t)N_NODES*KT2];   // [N][7680]  (hi|lo)
__device__ __nv_bfloat16 g_B3[(size_t)KT*DIM];        // [11520][768] (hi;hi;lo)
__device__ float g_norm[N_EDGES];
__device__ int   g_deg[NUM_REL*N_NODES];

// ---------------- helpers ---------------------------------------------------
__device__ __forceinline__ uint32_t sptr(const void* p) {
    return (uint32_t)__cvta_generic_to_shared(p);
}
__device__ __forceinline__ void cpa16(uint32_t s, const void* g, int sz) {
    asm volatile("cp.async.cg.shared.global [%0], [%1], 16, %2;\n"
                 :: "r"(s), "l"(g), "r"(sz));
}
__device__ __forceinline__ const float* pick_x(const float* ext, int sel) {
    return sel == 0 ? g_x0 : (sel == 1 ? g_x1 : ext);
}

// ---------------- small kernels ---------------------------------------------
__global__ void k_zero_deg() {
    int i = blockIdx.x * blockDim.x + threadIdx.x;
    if (i < NUM_REL * N_NODES) g_deg[i] = 0;
}

__global__ void k_deg(const int* __restrict__ ei, const int* __restrict__ et) {
    int e = blockIdx.x * blockDim.x + threadIdx.x;
    if (e < N_EDGES) atomicAdd(&g_deg[et[e] * N_NODES + ei[N_EDGES + e]], 1);
}

__global__ void k_norm(const int* __restrict__ ei, const int* __restrict__ et) {
    int e = blockIdx.x * blockDim.x + threadIdx.x;
    if (e < N_EDGES) {
        int d = g_deg[et[e] * N_NODES + ei[N_EDGES + e]];
        g_norm[e] = 1.0f / (d > 1 ? (float)d : 1.0f);
    }
}

__global__ void k_zero_agg() {
    size_t n4 = (size_t)NUM_REL * N_NODES * DIM / 4;
    float4 z = make_float4(0.f, 0.f, 0.f, 0.f);
    for (size_t i = blockIdx.x * (size_t)blockDim.x + threadIdx.x; i < n4;
         i += (size_t)gridDim.x * blockDim.x)
        reinterpret_cast<float4*>(g_agg)[i] = z;
}

// one block (192 thr) per edge: agg[r][dst] += norm * x[src]
__global__ void k_scatter(const float* __restrict__ x_ext, int xsel,
                          const int* __restrict__ ei, const int* __restrict__ et) {
    const float* x = pick_x(x_ext, xsel);
    int e   = blockIdx.x;
    int src = ei[e];
    int dst = ei[N_EDGES + e];
    int r   = et[e];
    float w = g_norm[e];
    const float4* xs = reinterpret_cast<const float4*>(x + (size_t)src * DIM);
    float* ag = g_agg + ((size_t)r * N_NODES + dst) * DIM;
    float4 v = xs[threadIdx.x];
    int c = threadIdx.x * 4;
    atomicAdd(ag + c + 0, v.x * w);
    atomicAdd(ag + c + 1, v.y * w);
    atomicAdd(ag + c + 2, v.z * w);
    atomicAdd(ag + c + 3, v.w * w);
}

// build A' = [hi(x|agg) | lo(x|agg)] in bf16
__global__ void k_convA(const float* __restrict__ x_ext, int xsel) {
    const float* x = pick_x(x_ext, xsel);
    size_t idx = blockIdx.x * (size_t)blockDim.x + threadIdx.x;
    if (idx >= (size_t)N_NODES * K5) return;
    int    k5 = (int)(idx % K5);
    size_t i  = idx / K5;
    float a;
    if (k5 < DIM) {
        a = x[i * DIM + k5];
    } else {
        int r  = (k5 - DIM) / DIM;
        int kk = (k5 - DIM) - r * DIM;
        a = g_agg[((size_t)r * N_NODES + i) * DIM + kk];
    }
    __nv_bfloat16 hi = __float2bfloat16(a);
    __nv_bfloat16 lo = __float2bfloat16(a - __bfloat162float(hi));
    __nv_bfloat16* row = g_A3 + i * (size_t)KT2;
    row[k5]      = hi;
    row[K5 + k5] = lo;
}

// build B' = [hi; hi; lo] of [root; W0..W3]
__global__ void k_convB(const float* __restrict__ root, const float* __restrict__ W) {
    size_t idx = blockIdx.x * (size_t)blockDim.x + threadIdx.x;
    if (idx >= (size_t)K5 * DIM) return;
    int n = (int)(idx % DIM);
    int k = (int)(idx / DIM);
    float a = (k < DIM) ? root[(size_t)k * DIM + n]
                        : W[(size_t)(k - DIM) * DIM + n];  // W is [4][D][D] contiguous
    __nv_bfloat16 hi = __float2bfloat16(a);
    __nv_bfloat16 lo = __float2bfloat16(a - __bfloat162float(hi));
    g_B3[(size_t)k * DIM + n]            = hi;
    g_B3[((size_t)K5 + k) * DIM + n]     = hi;
    g_B3[((size_t)2 * K5 + k) * DIM + n] = lo;
}

// ---------------- GEMM: C[N x 768] = A'[N x 11520] @ B'[11520 x 768] + bias -
#define BM 128
#define BN 128
#define APAD 8
#define BPAD 8

__global__ __launch_bounds__(256) void k_gemm(const float* __restrict__ bias,
                                              float* __restrict__ dout, int outsel,
                                              int relu) {
    __shared__ __nv_bfloat16 As[2][BM][BK + APAD];   // stride 40 elems = 80B (16B-aligned, cf-free)
    __shared__ __nv_bfloat16 Bs[2][BK][BN + BPAD];   // stride 136 elems = 272B

    float* C = outsel == 0 ? g_x0 : (outsel == 1 ? g_x1 : dout);

    const int ntile = blockIdx.x, mtile = blockIdx.y;
    const int tid = threadIdx.x, lane = tid & 31, warp = tid >> 5;
    const int wm = warp >> 1, wn = warp & 1;   // 4x2 warp grid, warp tile 32x64
    const int m_base = mtile * BM;

    float acc[2][8][4];
#pragma unroll
    for (int a = 0; a < 2; a++)
#pragma unroll
        for (int b = 0; b < 8; b++)
#pragma unroll
            for (int c = 0; c < 4; c++) acc[a][b][c] = 0.f;

    const int a_row = tid >> 2, a_col = (tid & 3) * 8;
    const int b_row = tid >> 4, b_col = (tid & 15) * 8;

    auto load_stage = [&](int kt, int buf) {
        // A: third logical block re-reads the physical hi block
        size_t kcolA = (size_t)((kt < HI2_TILES) ? kt : (kt - HI2_TILES)) * BK;
        size_t kcolB = (size_t)kt * BK;
#pragma unroll
        for (int i = 0; i < 2; i++) {
            int row  = a_row + i * 64;
            int grow = m_base + row;
            int ok   = grow < N_NODES;
            const __nv_bfloat16* src =
                g_A3 + (size_t)(ok ? grow : 0) * KT2 + kcolA + a_col;
            cpa16(sptr(&As[buf][row][a_col]), src, ok ? 16 : 0);  // zfill OOB rows
        }
#pragma unroll
        for (int i = 0; i < 2; i++) {
            int row = b_row + i * 16;
            const __nv_bfloat16* src =
                g_B3 + (kcolB + row) * DIM + (size_t)ntile * BN + b_col;
            cpa16(sptr(&Bs[buf][row][b_col]), src, 16);
        }
        asm volatile("cp.async.commit_group;\n");
    };

    auto compute = [&](int buf) {
#pragma unroll
        for (int ks = 0; ks < BK; ks += 16) {
            uint32_t af[2][4];
#pragma unroll
            for (int mi = 0; mi < 2; mi++) {
                uint32_t addr = sptr(&As[buf][wm * 32 + mi * 16 + (lane & 15)]
                                       [ks + (lane >> 4) * 8]);
                asm volatile(
                    "ldmatrix.sync.aligned.m8n8.x4.shared.b16 {%0,%1,%2,%3}, [%4];\n"
                    : "=r"(af[mi][0]), "=r"(af[mi][1]), "=r"(af[mi][2]), "=r"(af[mi][3])
                    : "r"(addr));
            }
            uint32_t bf[8][2];
#pragma unroll
            for (int nj = 0; nj < 4; nj++) {
                uint32_t addr = sptr(&Bs[buf][ks + (lane & 15)]
                                       [wn * 64 + nj * 16 + (lane >> 4) * 8]);
                asm volatile(
                    "ldmatrix.sync.aligned.m8n8.x4.trans.shared.b16 {%0,%1,%2,%3}, [%4];\n"
                    : "=r"(bf[2 * nj][0]), "=r"(bf[2 * nj][1]),
                      "=r"(bf[2 * nj + 1][0]), "=r"(bf[2 * nj + 1][1])
                    : "r"(addr));
            }
#pragma unroll
            for (int mi = 0; mi < 2; mi++)
#pragma unroll
                for (int ni = 0; ni < 8; ni++)
                    asm volatile(
                        "mma.sync.aligned.m16n8k16.row.col.f32.bf16.bf16.f32 "
                        "{%0,%1,%2,%3}, {%4,%5,%6,%7}, {%8,%9}, {%0,%1,%2,%3};\n"
                        : "+f"(acc[mi][ni][0]), "+f"(acc[mi][ni][1]),
                          "+f"(acc[mi][ni][2]), "+f"(acc[mi][ni][3])
                        : "r"(af[mi][0]), "r"(af[mi][1]), "r"(af[mi][2]), "r"(af[mi][3]),
                          "r"(bf[ni][0]), "r"(bf[ni][1]));
        }
    };

    load_stage(0, 0);
    for (int kt = 0; kt < NKT; ++kt) {
        int cur = kt & 1;
        if (kt + 1 < NKT) {
            load_stage(kt + 1, cur ^ 1);
            asm volatile("cp.async.wait_group 1;\n");
        } else {
            asm volatile("cp.async.wait_group 0;\n");
        }
        __syncthreads();
        compute(cur);
        __syncthreads();
    }

    // epilogue: bias (+relu), fp32 store
    const int g = lane >> 2, t4 = lane & 3;
#pragma unroll
    for (int mi = 0; mi < 2; mi++) {
#pragma unroll
        for (int ni = 0; ni < 8; ni++) {
            int col = ntile * BN + wn * 64 + ni * 8 + 2 * t4;
            float b0 = bias[col], b1 = bias[col + 1];
            float v0 = acc[mi][ni][0] + b0, v1 = acc[mi][ni][1] + b1;
            float v2 = acc[mi][ni][2] + b0, v3 = acc[mi][ni][3] + b1;
            if (relu) {
                v0 = fmaxf(v0, 0.f); v1 = fmaxf(v1, 0.f);
                v2 = fmaxf(v2, 0.f); v3 = fmaxf(v3, 0.f);
            }
            int r0 = m_base + wm * 32 + mi * 16 + g;
            if (r0 < N_NODES)
                *reinterpret_cast<float2*>(C + (size_t)r0 * DIM + col) = make_float2(v0, v1);
            int r1 = r0 + 8;
            if (r1 < N_NODES)
                *reinterpret_cast<float2*>(C + (size_t)r1 * DIM + col) = make_float2(v2, v3);
        }
    }
}

// ---------------- launch -----------------------------------------------------
extern "C" void kernel_launch(void* const* d_in, const int* in_sizes, int n_in,
                              void* d_out, int out_size) {
    const float* entity = (const float*)d_in[0];
    const int*   ei     = (const int*)d_in[1];   // [2][E]: row0=src, row1=dst (JAX int64 -> int32, x64 disabled)
    const int*   et     = (const int*)d_in[2];
    const float* Ws[3]    = {(const float*)d_in[3], (const float*)d_in[6], (const float*)d_in[9]};
    const float* roots[3] = {(const float*)d_in[4], (const float*)d_in[7], (const float*)d_in[10]};
    const float* bs[3]    = {(const float*)d_in[5], (const float*)d_in[8], (const float*)d_in[11]};
    (void)in_sizes; (void)n_in; (void)out_size;

    // graph-invariant per-edge mean weights
    k_zero_deg<<<(NUM_REL * N_NODES + 255) / 256, 256>>>();
    k_deg<<<(N_EDGES + 255) / 256, 256>>>(ei, et);
    k_norm<<<(N_EDGES + 255) / 256, 256>>>(ei, et);

    dim3 ggrid(DIM / BN, (N_NODES + BM - 1) / BM);  // (6, 157)
    // layer L: input sel (2=external entity, 0=g_x0, 1=g_x1); output sel (0,1,2=d_out)
    int xsel[3]   = {2, 0, 1};
    int outsel[3] = {0, 1, 2};
    for (int L = 0; L < 3; ++L) {
        k_zero_agg<<<2048, 256>>>();
        k_scatter<<<N_EDGES, 192>>>(entity, xsel[L], ei, et);
        k_convA<<<(int)(((size_t)N_NODES * K5 + 255) / 256), 256>>>(entity, xsel[L]);
        k_convB<<<(int)(((size_t)K5 * DIM + 255) / 256), 256>>>(roots[L], Ws[L]);
        k_gemm<<<ggrid, 256>>>(bs[L], (float*)d_out, outsel[L], L < 2 ? 1 : 0);
    }
}

// round 4
// speedup vs baseline: 1.2300x; 1.2300x over previous
#include <cuda_runtime.h>
#include <cuda_bf16.h>
#include <cstdint>

#define N_NODES 20000
#define N_EDGES 100000
#define DIM 768
#define NUM_REL 4
#define NBINS (NUM_REL*N_NODES)      // 80000
#define K5  (5*DIM)                  // 3840: [x | agg0..agg3]
#define KT2 (2*K5)                   // 7680: physical cols [hi | lo]
#define KT  (3*K5)                   // 11520: logical K [hi | lo | hi]
#define BKT 64
#define NKT (KT/BKT)                 // 180 k-tiles
#define BM 128
#define BN 256
#define NTHR 512
#define NST 4
#define A_STRIDE (BKT+8)             // 72 elems
#define B_STRIDE (BN+8)              // 264 elems
#define STAGE_A_BYTES (BM*A_STRIDE*2)            // 18432
#define STAGE_B_BYTES (BKT*B_STRIDE*2)           // 33792
#define STAGE_BYTES (STAGE_A_BYTES+STAGE_B_BYTES)// 52224
#define SMEM_DYN (NST*STAGE_BYTES + 1024)        // 209920

// ---------------- scratch -----------------------------------------------------
__device__ float g_x0[(size_t)N_NODES*DIM];
__device__ float g_x1[(size_t)N_NODES*DIM];
__device__ __nv_bfloat16 g_A3[(size_t)N_NODES*KT2];   // [N][7680] (hi|lo) K-major
__device__ __nv_bfloat16 g_B3[(size_t)KT2*DIM];       // [7680][768] (hi;lo) rows=k
__device__ int g_deg[NBINS];
__device__ int g_ptr[NBINS+1];
__device__ int g_cursor[NBINS];
__device__ int g_esrc[N_EDGES];

// ---------------- helpers -----------------------------------------------------
__device__ __forceinline__ uint32_t sptr(const void* p) {
    return (uint32_t)__cvta_generic_to_shared(p);
}
__device__ __forceinline__ void cpa16(uint32_t s, const void* g, int sz) {
    asm volatile("cp.async.cg.shared.global [%0], [%1], 16, %2;\n"
                 :: "r"(s), "l"(g), "r"(sz));
}
__device__ __forceinline__ const float* pick_x(const float* ext, int sel) {
    return sel == 0 ? g_x0 : (sel == 1 ? g_x1 : ext);
}
__device__ __forceinline__ void store_hilo(__nv_bfloat16* row, int off, float4 v) {
    __nv_bfloat16 h0 = __float2bfloat16(v.x), h1 = __float2bfloat16(v.y);
    __nv_bfloat16 h2 = __float2bfloat16(v.z), h3 = __float2bfloat16(v.w);
    __nv_bfloat16 l0 = __float2bfloat16(v.x - __bfloat162float(h0));
    __nv_bfloat16 l1 = __float2bfloat16(v.y - __bfloat162float(h1));
    __nv_bfloat16 l2 = __float2bfloat16(v.z - __bfloat162float(h2));
    __nv_bfloat16 l3 = __float2bfloat16(v.w - __bfloat162float(h3));
    __nv_bfloat162 hp0 = {h0, h1}, hp1 = {h2, h3}, lp0 = {l0, l1}, lp1 = {l2, l3};
    uint2 hv, lv;
    hv.x = *reinterpret_cast<uint32_t*>(&hp0); hv.y = *reinterpret_cast<uint32_t*>(&hp1);
    lv.x = *reinterpret_cast<uint32_t*>(&lp0); lv.y = *reinterpret_cast<uint32_t*>(&lp1);
    *reinterpret_cast<uint2*>(row + off)       = hv;
    *reinterpret_cast<uint2*>(row + K5 + off)  = lv;
}

// ---------------- graph prep (once per launch) --------------------------------
__global__ void k_zero_deg() {
    int i = blockIdx.x * blockDim.x + threadIdx.x;
    if (i < NBINS) g_deg[i] = 0;
}
__global__ void k_deg(const int* __restrict__ ei, const int* __restrict__ et) {
    int e = blockIdx.x * blockDim.x + threadIdx.x;
    if (e < N_EDGES) atomicAdd(&g_deg[et[e] * N_NODES + ei[N_EDGES + e]], 1);
}
// single-block exclusive scan over 80000 bins -> g_ptr, and init g_cursor
__global__ void k_scan() {
    __shared__ int buf[1024];
    __shared__ int carry;
    int tid = threadIdx.x;
    if (tid == 0) { carry = 0; g_ptr[0] = 0; }
    __syncthreads();
    for (int base = 0; base < NBINS; base += 1024) {
        int idx = base + tid;
        int v = (idx < NBINS) ? g_deg[idx] : 0;
        buf[tid] = v;
        __syncthreads();
#pragma unroll
        for (int off = 1; off < 1024; off <<= 1) {
            int t = (tid >= off) ? buf[tid - off] : 0;
            __syncthreads();
            buf[tid] += t;
            __syncthreads();
        }
        if (idx < NBINS) {
            int p = carry + buf[tid];
            g_ptr[idx + 1] = p;
            g_cursor[idx]  = p - v;   // exclusive start of bin idx
        }
        __syncthreads();
        if (tid == 0) carry += buf[1023];
        __syncthreads();
    }
}
__global__ void k_place(const int* __restrict__ ei, const int* __restrict__ et) {
    int e = blockIdx.x * blockDim.x + threadIdx.x;
    if (e < N_EDGES) {
        int b = et[e] * N_NODES + ei[N_EDGES + e];
        int pos = atomicAdd(&g_cursor[b], 1);
        g_esrc[pos] = ei[e];
    }
}

// ---------------- fused aggregate + bf16 hi/lo A' build -----------------------
// one block (192 thr) per dst node; thread owns 4 consecutive dims
__global__ __launch_bounds__(192) void k_agg(const float* __restrict__ x_ext, int xsel) {
    const float* x = pick_x(x_ext, xsel);
    int i = blockIdx.x;
    int c = threadIdx.x * 4;
    __nv_bfloat16* row = g_A3 + (size_t)i * KT2;

    // self term
    float4 vself = *reinterpret_cast<const float4*>(x + (size_t)i * DIM + c);
    store_hilo(row, c, vself);

#pragma unroll
    for (int r = 0; r < NUM_REL; r++) {
        int b = r * N_NODES + i;
        int s = g_ptr[b], e = g_ptr[b + 1];
        float4 a = make_float4(0.f, 0.f, 0.f, 0.f);
        for (int j = s; j < e; j++) {
            int src = g_esrc[j];
            float4 v = *reinterpret_cast<const float4*>(x + (size_t)src * DIM + c);
            a.x += v.x; a.y += v.y; a.z += v.z; a.w += v.w;
        }
        float w = (e > s) ? 1.0f / (float)(e - s) : 0.0f;
        a.x *= w; a.y *= w; a.z *= w; a.w *= w;
        store_hilo(row, DIM * (r + 1) + c, a);
    }
}

// ---------------- B' build: [hi(3840);lo(3840)] x 768, rows = k ---------------
__global__ void k_convB(const float* __restrict__ root, const float* __restrict__ W) {
    size_t idx = blockIdx.x * (size_t)blockDim.x + threadIdx.x;
    if (idx >= (size_t)K5 * DIM) return;
    int n = (int)(idx % DIM);
    int k = (int)(idx / DIM);
    float a = (k < DIM) ? root[(size_t)k * DIM + n]
                        : W[(size_t)(k - DIM) * DIM + n];   // W is [4][D][D] contiguous
    __nv_bfloat16 hi = __float2bfloat16(a);
    __nv_bfloat16 lo = __float2bfloat16(a - __bfloat162float(hi));
    g_B3[(size_t)k * DIM + n]            = hi;
    g_B3[((size_t)K5 + k) * DIM + n]     = lo;
}

// ---------------- GEMM: C[20000x768] = A'[. x 11520] @ B'[11520 x 768] + b ----
// 128x256x64 tiles, 512 thr (16 warps, 4x4), warp tile 32x64, 4-stage cp.async
__global__ __launch_bounds__(NTHR) void k_gemm(const float* __restrict__ bias,
                                               float* __restrict__ dout, int outsel,
                                               int relu) {
    extern __shared__ char dsm[];
    float* C = outsel == 0 ? g_x0 : (outsel == 1 ? g_x1 : dout);

    const int tid = threadIdx.x, lane = tid & 31, warp = tid >> 5;
    const int wm = warp >> 2, wn = warp & 3;          // 4x4 warps
    const int ntile = blockIdx.x, mtile = blockIdx.y;
    const int m_base = mtile * BM, n_base = ntile * BN;

    float acc[2][8][4];
#pragma unroll
    for (int a = 0; a < 2; a++)
#pragma unroll
        for (int b = 0; b < 8; b++)
#pragma unroll
            for (int c = 0; c < 4; c++) acc[a][b][c] = 0.f;

    auto stageA = [&](int s) -> char* { return dsm + s * STAGE_BYTES; };
    auto stageB = [&](int s) -> char* { return dsm + s * STAGE_BYTES + STAGE_A_BYTES; };

    auto load_tile = [&](int kt, int s) {
        size_t kA = (size_t)((kt < 120) ? kt : kt - 120) * BKT;  // [hi|lo|hi]
        size_t kB = (size_t)((kt < 60) ? kt : kt - 60) * BKT;    // [hi;hi;lo]
        uint32_t as = sptr(stageA(s)), bs = sptr(stageB(s));
#pragma unroll
        for (int i = 0; i < 2; i++) {                 // A: 1024 chunks of 16B
            int c = tid + i * NTHR;
            int row = c >> 3, kc = c & 7;
            int grow = m_base + row;
            int ok = grow < N_NODES;
            const __nv_bfloat16* src = g_A3 + (size_t)(ok ? grow : 0) * KT2 + kA + kc * 8;
            cpa16(as + (row * A_STRIDE + kc * 8) * 2, src, ok ? 16 : 0);
        }
#pragma unroll
        for (int i = 0; i < 4; i++) {                 // B: 2048 chunks of 16B
            int c = tid + i * NTHR;
            int rk = c >> 5, nc = (c & 31) * 8;
            const __nv_bfloat16* src = g_B3 + (kB + rk) * DIM + n_base + nc;
            cpa16(bs + (rk * B_STRIDE + nc) * 2, src, 16);
        }
        asm volatile("cp.async.commit_group;\n");
    };

    auto compute = [&](int s) {
        char* As = stageA(s);
        char* Bs = stageB(s);
#pragma unroll
        for (int ks = 0; ks < BKT; ks += 16) {
            uint32_t af[2][4];
#pragma unroll
            for (int mi = 0; mi < 2; mi++) {
                int rr = wm * 32 + mi * 16 + (lane & 15);
                int cc = ks + (lane >> 4) * 8;
                uint32_t addr = sptr(As + (rr * A_STRIDE + cc) * 2);
                asm volatile(
                    "ldmatrix.sync.aligned.m8n8.x4.shared.b16 {%0,%1,%2,%3}, [%4];\n"
                    : "=r"(af[mi][0]), "=r"(af[mi][1]), "=r"(af[mi][2]), "=r"(af[mi][3])
                    : "r"(addr));
            }
            uint32_t bf[8][2];
#pragma unroll
            for (int nj = 0; nj < 4; nj++) {
                int rr = ks + (lane & 15);
                int cc = wn * 64 + nj * 16 + (lane >> 4) * 8;
                uint32_t addr = sptr(Bs + (rr * B_STRIDE + cc) * 2);
                asm volatile(
                    "ldmatrix.sync.aligned.m8n8.x4.trans.shared.b16 {%0,%1,%2,%3}, [%4];\n"
                    : "=r"(bf[2 * nj][0]), "=r"(bf[2 * nj][1]),
                      "=r"(bf[2 * nj + 1][0]), "=r"(bf[2 * nj + 1][1])
                    : "r"(addr));
            }
#pragma unroll
            for (int mi = 0; mi < 2; mi++)
#pragma unroll
                for (int ni = 0; ni < 8; ni++)
                    asm volatile(
                        "mma.sync.aligned.m16n8k16.row.col.f32.bf16.bf16.f32 "
                        "{%0,%1,%2,%3}, {%4,%5,%6,%7}, {%8,%9}, {%0,%1,%2,%3};\n"
                        : "+f"(acc[mi][ni][0]), "+f"(acc[mi][ni][1]),
                          "+f"(acc[mi][ni][2]), "+f"(acc[mi][ni][3])
                        : "r"(af[mi][0]), "r"(af[mi][1]), "r"(af[mi][2]), "r"(af[mi][3]),
                          "r"(bf[ni][0]), "r"(bf[ni][1]));
        }
    };

    // prologue: tiles 0..2 into stages 0..2
    load_tile(0, 0);
    load_tile(1, 1);
    load_tile(2, 2);

    for (int kt = 0; kt < NKT; ++kt) {
        asm volatile("cp.async.wait_group 2;\n");   // tile kt resident
        __syncthreads();                            // all warps done with stage (kt-1)%4
        int nxt = kt + 3;
        if (nxt < NKT) load_tile(nxt, nxt & 3);
        else asm volatile("cp.async.commit_group;\n");  // keep group accounting
        compute(kt & 3);
    }

    // epilogue: bias (+relu), fp32 store
    const int g = lane >> 2, t4 = lane & 3;
#pragma unroll
    for (int mi = 0; mi < 2; mi++) {
#pragma unroll
        for (int ni = 0; ni < 8; ni++) {
            int col = n_base + wn * 64 + ni * 8 + 2 * t4;
            float b0 = bias[col], b1 = bias[col + 1];
            float v0 = acc[mi][ni][0] + b0, v1 = acc[mi][ni][1] + b1;
            float v2 = acc[mi][ni][2] + b0, v3 = acc[mi][ni][3] + b1;
            if (relu) {
                v0 = fmaxf(v0, 0.f); v1 = fmaxf(v1, 0.f);
                v2 = fmaxf(v2, 0.f); v3 = fmaxf(v3, 0.f);
            }
            int r0 = m_base + wm * 32 + mi * 16 + g;
            if (r0 < N_NODES)
                *reinterpret_cast<float2*>(C + (size_t)r0 * DIM + col) = make_float2(v0, v1);
            int r1 = r0 + 8;
            if (r1 < N_NODES)
                *reinterpret_cast<float2*>(C + (size_t)r1 * DIM + col) = make_float2(v2, v3);
        }
    }
}

// ---------------- launch ------------------------------------------------------
extern "C" void kernel_launch(void* const* d_in, const int* in_sizes, int n_in,
                              void* d_out, int out_size) {
    const float* entity = (const float*)d_in[0];
    const int* ei = (const int*)d_in[1];   // [2][E]: row0=src, row1=dst (int32 payload)
    const int* et = (const int*)d_in[2];
    const float* Ws[3]    = {(const float*)d_in[3], (const float*)d_in[6], (const float*)d_in[9]};
    const float* roots[3] = {(const float*)d_in[4], (const float*)d_in[7], (const float*)d_in[10]};
    const float* bs[3]    = {(const float*)d_in[5], (const float*)d_in[8], (const float*)d_in[11]};
    (void)in_sizes; (void)n_in; (void)out_size;

    cudaFuncSetAttribute(k_gemm, cudaFuncAttributeMaxDynamicSharedMemorySize, SMEM_DYN);

    // CSR by (rel,dst), built once per launch
    k_zero_deg<<<(NBINS + 255) / 256, 256>>>();
    k_deg<<<(N_EDGES + 255) / 256, 256>>>(ei, et);
    k_scan<<<1, 1024>>>();
    k_place<<<(N_EDGES + 255) / 256, 256>>>(ei, et);

    dim3 ggrid(DIM / BN, (N_NODES + BM - 1) / BM);   // (3, 157); ntile fastest -> A reuse in L2
    int xsel[3]   = {2, 0, 1};
    int outsel[3] = {0, 1, 2};
    for (int L = 0; L < 3; ++L) {
        k_agg<<<N_NODES, 192>>>(entity, xsel[L]);
        k_convB<<<(int)(((size_t)K5 * DIM + 255) / 256), 256>>>(roots[L], Ws[L]);
        k_gemm<<<ggrid, NTHR, SMEM_DYN>>>(bs[L], (float*)d_out, outsel[L], L < 2 ? 1 : 0);
    }
}

// round 5
// speedup vs baseline: 1.5933x; 1.2954x over previous
#include <cuda_runtime.h>
#include <cstdint>

#define N_NODES 20000
#define N_EDGES 100000
#define DIM 768
#define NUM_REL 4
#define NBINS (NUM_REL*N_NODES)      // 80000
#define K5  (5*DIM)                  // 3840
#define KA2 (2*K5)                   // 7680 physical cols [q1 | q0]
#define BKT 64
#define NKT 180                      // 60 (11-pass) + 120 (cross)
#define BM 128
#define BN 128
#define NTHR 256
#define NST 4
#define SROW 80                      // smem row stride (64 int8 + 16 pad)
#define STAGE_A (BM*SROW)            // 10240
#define STAGE_B (BN*SROW)            // 10240
#define STAGE_BYTES (STAGE_A+STAGE_B)// 20480
#define SMEM_DYN (NST*STAGE_BYTES)   // 81920
#define QMAXF 16256.0f

// ---------------- scratch -----------------------------------------------------
__device__ float g_x0[(size_t)N_NODES*DIM];
__device__ float g_x1[(size_t)N_NODES*DIM];
__device__ int8_t g_A8[(size_t)N_NODES*KA2];   // [N][7680]: [a1(3840)|a0(3840)] K-major
__device__ int8_t g_B8[(size_t)DIM*KA2];       // [768][7680]: [b1|b0] K-major (n-major rows)
__device__ float g_sA[N_NODES];
__device__ float g_sB[DIM];
__device__ int g_deg[NBINS];
__device__ int g_ptr[NBINS+1];
__device__ int g_cursor[NBINS];
__device__ int g_esrc[N_EDGES];

// ---------------- helpers -----------------------------------------------------
__device__ __forceinline__ uint32_t sptr(const void* p) {
    return (uint32_t)__cvta_generic_to_shared(p);
}
__device__ __forceinline__ void cpa16(uint32_t s, const void* g, int sz) {
    asm volatile("cp.async.cg.shared.global [%0], [%1], 16, %2;\n"
                 :: "r"(s), "l"(g), "r"(sz));
}
__device__ __forceinline__ const float* pick_x(const float* ext, int sel) {
    return sel == 0 ? g_x0 : (sel == 1 ? g_x1 : ext);
}
// 15-bit split quantize: v -> (q1, q0) with v ~= s*(128*q1+q0)
__device__ __forceinline__ void quant15(float v, float inv, int8_t& q1, int8_t& q0) {
    int q = __float2int_rn(v * inv);
    q = max(-16256, min(16256, q));
    int h = __float2int_rn((float)q * 0.0078125f);   // q/128, |h|<=127
    q1 = (int8_t)h;
    q0 = (int8_t)(q - (h << 7));                     // |q0|<=64
}

// ---------------- prep: zero+deg+scan in ONE single-block kernel ---------------
__global__ __launch_bounds__(1024) void k_prep(const int* __restrict__ ei,
                                               const int* __restrict__ et) {
    __shared__ int buf[1024];
    __shared__ int carry;
    int tid = threadIdx.x;
    for (int i = tid; i < NBINS; i += 1024) g_deg[i] = 0;
    __syncthreads();
    for (int e = tid; e < N_EDGES; e += 1024)
        atomicAdd(&g_deg[et[e] * N_NODES + ei[N_EDGES + e]], 1);
    __syncthreads();
    if (tid == 0) { carry = 0; g_ptr[0] = 0; }
    __syncthreads();
    for (int base = 0; base < NBINS; base += 1024) {
        int idx = base + tid;
        int v = (idx < NBINS) ? g_deg[idx] : 0;
        buf[tid] = v;
        __syncthreads();
#pragma unroll
        for (int off = 1; off < 1024; off <<= 1) {
            int t = (tid >= off) ? buf[tid - off] : 0;
            __syncthreads();
            buf[tid] += t;
            __syncthreads();
        }
        if (idx < NBINS) {
            int p = carry + buf[tid];
            g_ptr[idx + 1] = p;
            g_cursor[idx]  = p - v;
        }
        __syncthreads();
        if (tid == 0) carry += buf[1023];
        __syncthreads();
    }
}
__global__ void k_place(const int* __restrict__ ei, const int* __restrict__ et) {
    int e = blockIdx.x * blockDim.x + threadIdx.x;
    if (e < N_EDGES) {
        int b = et[e] * N_NODES + ei[N_EDGES + e];
        int pos = atomicAdd(&g_cursor[b], 1);
        g_esrc[pos] = ei[e];
    }
}

// ---------------- fused: aggregate+quantize A  AND  quantize B ----------------
// blocks [0, N_NODES): node agg; blocks [N_NODES, N_NODES+DIM): B column quant
__global__ __launch_bounds__(256) void k_aggconv(const float* __restrict__ x_ext, int xsel,
                                                 const float* __restrict__ root,
                                                 const float* __restrict__ W) {
    __shared__ float rbuf[256];
    int tid = threadIdx.x;
    int b = blockIdx.x;

    if (b < N_NODES) {
        const float* x = pick_x(x_ext, xsel);
        int i = b;
        int c0 = tid * 3;                       // 256*3 = 768 dims
        float v[5][3];
        {
            const float* xp = x + (size_t)i * DIM + c0;
            v[0][0] = xp[0]; v[0][1] = xp[1]; v[0][2] = xp[2];
        }
#pragma unroll
        for (int r = 0; r < NUM_REL; r++) {
            int bb = r * N_NODES + i;
            int s = g_ptr[bb], e = g_ptr[bb + 1];
            float a0 = 0.f, a1 = 0.f, a2 = 0.f;
            for (int j = s; j < e; j++) {
                const float* q = x + (size_t)g_esrc[j] * DIM + c0;
                a0 += q[0]; a1 += q[1]; a2 += q[2];
            }
            float w = (e > s) ? 1.0f / (float)(e - s) : 0.0f;
            v[r + 1][0] = a0 * w; v[r + 1][1] = a1 * w; v[r + 1][2] = a2 * w;
        }
        float m = 0.f;
#pragma unroll
        for (int s = 0; s < 5; s++)
#pragma unroll
            for (int j = 0; j < 3; j++) m = fmaxf(m, fabsf(v[s][j]));
        rbuf[tid] = m;
        __syncthreads();
        for (int o = 128; o > 0; o >>= 1) {
            if (tid < o) rbuf[tid] = fmaxf(rbuf[tid], rbuf[tid + o]);
            __syncthreads();
        }
        m = rbuf[0];
        float inv = (m > 0.f) ? QMAXF / m : 0.f;
        if (tid == 0) g_sA[i] = m * (1.0f / QMAXF);
        int8_t* rowp = g_A8 + (size_t)i * KA2;
#pragma unroll
        for (int s = 0; s < 5; s++) {
            int col = s * DIM + c0;
#pragma unroll
            for (int j = 0; j < 3; j++) {
                int8_t q1, q0;
                quant15(v[s][j], inv, q1, q0);
                rowp[col + j]      = q1;
                rowp[K5 + col + j] = q0;
            }
        }
    } else {
        int n = b - N_NODES;                    // 0..767
        float vals[15];                         // K5/256
        float m = 0.f;
#pragma unroll
        for (int t = 0; t < 15; t++) {
            int k = tid + t * 256;
            float a = (k < DIM) ? root[(size_t)k * DIM + n]
                                : W[(size_t)(k - DIM) * DIM + n];
            vals[t] = a;
            m = fmaxf(m, fabsf(a));
        }
        rbuf[tid] = m;
        __syncthreads();
        for (int o = 128; o > 0; o >>= 1) {
            if (tid < o) rbuf[tid] = fmaxf(rbuf[tid], rbuf[tid + o]);
            __syncthreads();
        }
        m = rbuf[0];
        float inv = (m > 0.f) ? QMAXF / m : 0.f;
        if (tid == 0) g_sB[n] = m * (1.0f / QMAXF);
        int8_t* rowp = g_B8 + (size_t)n * KA2;
#pragma unroll
        for (int t = 0; t < 15; t++) {
            int k = tid + t * 256;
            int8_t q1, q0;
            quant15(vals[t], inv, q1, q0);
            rowp[k]      = q1;
            rowp[K5 + k] = q0;
        }
    }
}

// ---------------- int8 IMMA GEMM ----------------------------------------------
// C[20000x768] = sA .* ( 16384*A1B1 + 128*(A1B0 + A0B1) ) .* sB + bias
// tiles 128x128x64, 256 thr (8 warps: 4m x 2n), warp tile 32x64, 4-stage cp.async
__global__ __launch_bounds__(NTHR) void k_gemm(const float* __restrict__ bias,
                                               float* __restrict__ dout, int outsel,
                                               int relu) {
    extern __shared__ char dsm[];
    float* C = outsel == 0 ? g_x0 : (outsel == 1 ? g_x1 : dout);

    const int tid = threadIdx.x, lane = tid & 31, warp = tid >> 5;
    const int wm = warp >> 1, wn = warp & 1;
    const int ntile = blockIdx.x, mtile = blockIdx.y;
    const int m_base = mtile * BM, n_base = ntile * BN;

    int acc11[2][8][4], accX[2][8][4];
#pragma unroll
    for (int a = 0; a < 2; a++)
#pragma unroll
        for (int b = 0; b < 8; b++)
#pragma unroll
            for (int c = 0; c < 4; c++) { acc11[a][b][c] = 0; accX[a][b][c] = 0; }

    auto load_tile = [&](int kt, int s) {
        int kA, kB;
        if (kt < 60) { kA = kt * BKT; kB = kt * BKT; }               // A1 x B1
        else {
            int k2 = kt - 60;                                        // cross pass
            kA = k2 * BKT;                                           // [A1|A0]
            kB = (k2 < 60) ? K5 + k2 * BKT : (k2 - 60) * BKT;        // [B0;B1]
        }
        uint32_t as = sptr(dsm + s * STAGE_BYTES);
        uint32_t bs2 = as + STAGE_A;
#pragma unroll
        for (int i = 0; i < 2; i++) {                 // A: 512 chunks of 16B
            int c = tid + i * NTHR;
            int row = c >> 2, kc = c & 3;
            int grow = m_base + row;
            int ok = grow < N_NODES;
            const int8_t* src = g_A8 + (size_t)(ok ? grow : 0) * KA2 + kA + kc * 16;
            cpa16(as + row * SROW + kc * 16, src, ok ? 16 : 0);
        }
#pragma unroll
        for (int i = 0; i < 2; i++) {                 // B: 512 chunks of 16B
            int c = tid + i * NTHR;
            int row = c >> 2, kc = c & 3;
            const int8_t* src = g_B8 + (size_t)(n_base + row) * KA2 + kB + kc * 16;
            cpa16(bs2 + row * SROW + kc * 16, src, 16);
        }
        asm volatile("cp.async.commit_group;\n");
    };

    auto compute = [&](int s, int (&acc)[2][8][4]) {
        char* As = dsm + s * STAGE_BYTES;
        char* Bs = As + STAGE_A;
#pragma unroll
        for (int ks = 0; ks < BKT; ks += 32) {
            uint32_t af[2][4];
#pragma unroll
            for (int mi = 0; mi < 2; mi++) {
                int rr = wm * 32 + mi * 16 + (lane & 15);
                int cb = ks + ((lane >> 4) << 4);
                uint32_t addr = sptr(As + rr * SROW + cb);
                asm volatile(
                    "ldmatrix.sync.aligned.m8n8.x4.shared.b16 {%0,%1,%2,%3}, [%4];\n"
                    : "=r"(af[mi][0]), "=r"(af[mi][1]), "=r"(af[mi][2]), "=r"(af[mi][3])
                    : "r"(addr));
            }
            uint32_t bf[8][2];
#pragma unroll
            for (int j = 0; j < 4; j++) {
                int n_off = j * 16 + ((lane >> 4) << 3) + (lane & 7);
                int cb = ks + (((lane >> 3) & 1) << 4);
                uint32_t addr = sptr(Bs + (wn * 64 + n_off) * SROW + cb);
                asm volatile(
                    "ldmatrix.sync.aligned.m8n8.x4.shared.b16 {%0,%1,%2,%3}, [%4];\n"
                    : "=r"(bf[2 * j][0]), "=r"(bf[2 * j][1]),
                      "=r"(bf[2 * j + 1][0]), "=r"(bf[2 * j + 1][1])
                    : "r"(addr));
            }
#pragma unroll
            for (int mi = 0; mi < 2; mi++)
#pragma unroll
                for (int ni = 0; ni < 8; ni++)
                    asm volatile(
                        "mma.sync.aligned.m16n8k32.row.col.s32.s8.s8.s32 "
                        "{%0,%1,%2,%3}, {%4,%5,%6,%7}, {%8,%9}, {%0,%1,%2,%3};\n"
                        : "+r"(acc[mi][ni][0]), "+r"(acc[mi][ni][1]),
                          "+r"(acc[mi][ni][2]), "+r"(acc[mi][ni][3])
                        : "r"(af[mi][0]), "r"(af[mi][1]), "r"(af[mi][2]), "r"(af[mi][3]),
                          "r"(bf[ni][0]), "r"(bf[ni][1]));
        }
    };

    load_tile(0, 0);
    load_tile(1, 1);
    load_tile(2, 2);

    for (int kt = 0; kt < NKT; ++kt) {
        asm volatile("cp.async.wait_group 2;\n");
        __syncthreads();
        int nxt = kt + 3;
        if (nxt < NKT) load_tile(nxt, nxt & 3);
        else asm volatile("cp.async.commit_group;\n");
        if (kt < 60) compute(kt & 3, acc11);
        else         compute(kt & 3, accX);
    }

    // epilogue: out = sA*sB*(16384*acc11 + 128*accX) + bias  (+relu)
    const int g = lane >> 2, t4 = lane & 3;
#pragma unroll
    for (int mi = 0; mi < 2; mi++) {
        int r0 = m_base + wm * 32 + mi * 16 + g;
        int r1 = r0 + 8;
        float sa0 = (r0 < N_NODES) ? g_sA[r0] : 0.f;
        float sa1 = (r1 < N_NODES) ? g_sA[r1] : 0.f;
#pragma unroll
        for (int ni = 0; ni < 8; ni++) {
            int col = n_base + wn * 64 + ni * 8 + 2 * t4;
            float sb0 = g_sB[col], sb1 = g_sB[col + 1];
            float b0 = bias[col], b1 = bias[col + 1];
            float v0 = sa0 * sb0 * (16384.f * (float)acc11[mi][ni][0] + 128.f * (float)accX[mi][ni][0]) + b0;
            float v1 = sa0 * sb1 * (16384.f * (float)acc11[mi][ni][1] + 128.f * (float)accX[mi][ni][1]) + b1;
            float v2 = sa1 * sb0 * (16384.f * (float)acc11[mi][ni][2] + 128.f * (float)accX[mi][ni][2]) + b0;
            float v3 = sa1 * sb1 * (16384.f * (float)acc11[mi][ni][3] + 128.f * (float)accX[mi][ni][3]) + b1;
            if (relu) {
                v0 = fmaxf(v0, 0.f); v1 = fmaxf(v1, 0.f);
                v2 = fmaxf(v2, 0.f); v3 = fmaxf(v3, 0.f);
            }
            if (r0 < N_NODES)
                *reinterpret_cast<float2*>(C + (size_t)r0 * DIM + col) = make_float2(v0, v1);
            if (r1 < N_NODES)
                *reinterpret_cast<float2*>(C + (size_t)r1 * DIM + col) = make_float2(v2, v3);
        }
    }
}

// ---------------- launch ------------------------------------------------------
extern "C" void kernel_launch(void* const* d_in, const int* in_sizes, int n_in,
                              void* d_out, int out_size) {
    const float* entity = (const float*)d_in[0];
    const int* ei = (const int*)d_in[1];
    const int* et = (const int*)d_in[2];
    const float* Ws[3]    = {(const float*)d_in[3], (const float*)d_in[6], (const float*)d_in[9]};
    const float* roots[3] = {(const float*)d_in[4], (const float*)d_in[7], (const float*)d_in[10]};
    const float* bs[3]    = {(const float*)d_in[5], (const float*)d_in[8], (const float*)d_in[11]};
    (void)in_sizes; (void)n_in; (void)out_size;

    cudaFuncSetAttribute(k_gemm, cudaFuncAttributeMaxDynamicSharedMemorySize, SMEM_DYN);

    k_prep<<<1, 1024>>>(ei, et);                       // launch 1
    k_place<<<(N_EDGES + 255) / 256, 256>>>(ei, et);   // launch 2

    dim3 ggrid(DIM / BN, (N_NODES + BM - 1) / BM);     // (6, 157)
    int xsel[3]   = {2, 0, 1};
    int outsel[3] = {0, 1, 2};
    for (int L = 0; L < 3; ++L) {
        k_aggconv<<<N_NODES + DIM, 256>>>(entity, xsel[L], roots[L], Ws[L]); // 3,5,7
        k_gemm<<<ggrid, NTHR, SMEM_DYN>>>(bs[L], (float*)d_out, outsel[L],   // 4,6,8
                                          L < 2 ? 1 : 0);
    }
}